// round 16
// baseline (speedup 1.0000x reference)
#include <cuda_runtime.h>
#include <cuda_fp16.h>
#include <cstdint>

typedef unsigned long long u64;

#define TT    64
#define BATCH 8192
#define DIN   128

#define G1 128
#define G2 64
#define G3 32
#define H1 32
#define H2 16
#define H3 8

// ---------------- phase A (mma.sync fp16 2-pass GEMM, M=64 tiles) ----------------
#define NTM_A 256
#define TPB_A 8
#define NBLK_A 1024                     // 8192 tiles / 8
#define PW 68                           // smem pitch in 32-bit words
#define XH_OFF 0                        // 64 rows (fp16 hi of x)
#define XL_OFF (64 * PW * 4)            // 17408 (fp16 lo of x)
#define WH_OFF (2 * 64 * PW * 4)        // 34816 (128 rows, fp16 W)
#define A_SMEM_BYTES (WH_OFF + 128 * PW * 4)   // 69632 -> 3 CTAs/SM

// ---------------- phase B (recurrent, BT=32, warp-specialized; R12 config) ----------------
#define BTB  32
#define NCTA_B (BATCH / BTB)
#define NTB 512
#define HP 36
#define H1SZ (H1 * HP)
#define H2SZ (H2 * HP)
#define H3SZ (H3 * HP)
#define OFFB_W1HI 0
#define OFFB_W2XI 4096
#define OFFB_W2HI 6144
#define OFFB_B2I  7168
#define OFFB_W3XI 7232
#define OFFB_W3HI 7744
#define OFFB_B3I  8000
#define OFFB_H1   8032
#define OFFB_H2   (OFFB_H1 + 2 * H1SZ)
#define OFFB_H3   (OFFB_H2 + 2 * H2SZ)
#define B_SMEM_FLOATS (OFFB_H3 + 2 * H3SZ)
#define B_SMEM_BYTES  (B_SMEM_FLOATS * 4)

// 256 MB scratch: XG[r = b*64 + t][n = 4j+q]  (row-major, bias folded in)
__device__ float g_xg[(size_t)BATCH * TT * G1];

// ======================= common helpers =======================
__device__ __forceinline__ u64 pack2(float a, float b) {
    u64 r;
    asm("mov.b64 %0, {%1, %2};" : "=l"(r) : "f"(a), "f"(b));
    return r;
}
__device__ __forceinline__ u64 fma2(u64 a, u64 b, u64 c) {
    u64 d;
    asm("fma.rn.f32x2 %0, %1, %2, %3;" : "=l"(d) : "l"(a), "l"(b), "l"(c));
    return d;
}
__device__ __forceinline__ float2 u2f2(u64 v) {
    float2 r;
    asm("mov.b64 {%0, %1}, %2;" : "=f"(r.x), "=f"(r.y) : "l"(v));
    return r;
}
__device__ __forceinline__ float sigf(float v) {
    return __fdividef(1.f, 1.f + __expf(-v));
}
__device__ __forceinline__ float tanhf_(float v) {
    return 1.f - __fdividef(2.f, __expf(2.f * v) + 1.f);
}

__device__ __forceinline__ void mma_f16(float (&d)[4],
                                        uint32_t a0, uint32_t a1,
                                        uint32_t a2, uint32_t a3,
                                        uint32_t b0, uint32_t b1) {
    asm volatile(
        "mma.sync.aligned.m16n8k16.row.col.f32.f16.f16.f32 "
        "{%0,%1,%2,%3}, {%4,%5,%6,%7}, {%8,%9}, {%0,%1,%2,%3};"
        : "+f"(d[0]), "+f"(d[1]), "+f"(d[2]), "+f"(d[3])
        : "r"(a0), "r"(a1), "r"(a2), "r"(a3), "r"(b0), "r"(b1));
}

// convert float4 into fp16 hi/lo half2 word pairs
__device__ __forceinline__ void cvt4hl(float4 v, uint32_t* H, uint32_t* L) {
    __half2 h0 = __float22half2_rn(make_float2(v.x, v.y));
    float2 f0 = __half22float2(h0);
    __half2 l0 = __float22half2_rn(make_float2(v.x - f0.x, v.y - f0.y));
    __half2 h1 = __float22half2_rn(make_float2(v.z, v.w));
    float2 f1 = __half22float2(h1);
    __half2 l1 = __float22half2_rn(make_float2(v.z - f1.x, v.w - f1.y));
    H[0] = *(uint32_t*)&h0;
    H[1] = *(uint32_t*)&h1;
    L[0] = *(uint32_t*)&l0;
    L[1] = *(uint32_t*)&l1;
}
// convert float4 into fp16 word pair (hi only)
__device__ __forceinline__ void cvt4h(float4 v, uint32_t* H) {
    __half2 h0 = __float22half2_rn(make_float2(v.x, v.y));
    __half2 h1 = __float22half2_rn(make_float2(v.z, v.w));
    H[0] = *(uint32_t*)&h0;
    H[1] = *(uint32_t*)&h1;
}

// ======================= PHASE A (HMMA fp16 2-pass, M=64, x reg-prefetch) =======================
// XG[r][4j+q] = sum_k x[r][k] * w_ih1[q*32+j][k] + b1[q*32+j]
// x = xh + xl (fp16 split); W = fp16(W). D = xh@wh + xl@wh.
extern __shared__ char smA[];
__global__ __launch_bounds__(NTM_A, 3) void lstm_phaseA_mma(
    const float* __restrict__ x,
    const float* __restrict__ w_ih1,
    const float* __restrict__ b_ih1,
    const float* __restrict__ b_hh1) {
    uint32_t* XH = (uint32_t*)(smA + XH_OFF);
    uint32_t* XL = (uint32_t*)(smA + XL_OFF);
    uint32_t* WH = (uint32_t*)(smA + WH_OFF);

    const int tid = threadIdx.x;
    const int wid = tid >> 5, lid = tid & 31;
    const int g = lid >> 2, tig = lid & 3;
    const int m0w = (wid & 1) * 32;      // warp M offset (0 or 32)
    const int n0w = (wid >> 1) * 32;     // warp N offset (0..96)

    // bias for this thread's D columns (n, n+1) per n-frag
    float2 biasp[4];
#pragma unroll
    for (int nf = 0; nf < 4; nf++) {
        int n = n0w + nf * 8 + tig * 2;
        int ga = ((n & 3) << 5) + (n >> 2);
        int gb = (((n + 1) & 3) << 5) + ((n + 1) >> 2);
        biasp[nf].x = b_ih1[ga] + b_hh1[ga];
        biasp[nf].y = b_ih1[gb] + b_hh1[gb];
    }

    // stage W fp16 once: row n of W^T = w_ih1 row g(n)
    {
        int row = tid >> 1, c0 = (tid & 1) * 64;
        int gw = ((row & 3) << 5) + (row >> 2);
        const float* src = w_ih1 + (size_t)gw * DIN + c0;
        uint32_t* Hd = WH + row * PW + (c0 >> 1);
#pragma unroll
        for (int i = 0; i < 16; i++)
            cvt4h(((const float4*)src)[i], Hd + 2 * i);
    }

    // x staging: row = tid>>2 (0..63), c0 = (tid&3)*32
    const int xrow = tid >> 2;
    const int xc0 = (tid & 3) * 32;
    float4 xr[8];
#define LOADX_A(tt_)                                                        \
    {                                                                       \
        const float4* p = (const float4*)(x +                               \
            (((size_t)blockIdx.x * TPB_A + (tt_)) * 64 + xrow) * DIN + xc0); \
        _Pragma("unroll") for (int i = 0; i < 8; i++) xr[i] = p[i];         \
    }

    LOADX_A(0);

    for (int tt = 0; tt < TPB_A; tt++) {
        const size_t r0 = ((size_t)blockIdx.x * TPB_A + tt) * 64;
        // stage x tile tt from registers (convert + STS only)
        {
            uint32_t* Hd = XH + xrow * PW + (xc0 >> 1);
            uint32_t* Ld = XL + xrow * PW + (xc0 >> 1);
#pragma unroll
            for (int i = 0; i < 8; i++)
                cvt4hl(xr[i], Hd + 2 * i, Ld + 2 * i);
        }
        __syncthreads();   // W (first iter) + X(tt) staged

        // prefetch x for tile tt+1; covered by MMA + epilogue below
        if (tt + 1 < TPB_A) LOADX_A(tt + 1);

        float acc[2][4][4];
#pragma unroll
        for (int mi = 0; mi < 2; mi++)
#pragma unroll
            for (int nf = 0; nf < 4; nf++) {
                acc[mi][nf][0] = biasp[nf].x;
                acc[mi][nf][1] = biasp[nf].y;
                acc[mi][nf][2] = biasp[nf].x;
                acc[mi][nf][3] = biasp[nf].y;
            }

#pragma unroll
        for (int ks = 0; ks < 8; ks++) {
            uint32_t ah[2][4], al[2][4];
#pragma unroll
            for (int mi = 0; mi < 2; mi++) {
                int base = (m0w + mi * 16 + g) * PW + tig + ks * 8;
                ah[mi][0] = XH[base];
                ah[mi][1] = XH[base + 8 * PW];
                ah[mi][2] = XH[base + 4];
                ah[mi][3] = XH[base + 8 * PW + 4];
                al[mi][0] = XL[base];
                al[mi][1] = XL[base + 8 * PW];
                al[mi][2] = XL[base + 4];
                al[mi][3] = XL[base + 8 * PW + 4];
            }
#pragma unroll
            for (int nf = 0; nf < 4; nf++) {
                int wb = (n0w + nf * 8 + g) * PW + tig + ks * 8;
                uint32_t bh0 = WH[wb], bh1 = WH[wb + 4];
#pragma unroll
                for (int mi = 0; mi < 2; mi++) {
                    mma_f16(acc[mi][nf], ah[mi][0], ah[mi][1], ah[mi][2], ah[mi][3], bh0, bh1);
                    mma_f16(acc[mi][nf], al[mi][0], al[mi][1], al[mi][2], al[mi][3], bh0, bh1);
                }
            }
        }

        // epilogue: D frags straight to row-major XG
#pragma unroll
        for (int mi = 0; mi < 2; mi++) {
            size_t row = r0 + m0w + mi * 16 + g;
#pragma unroll
            for (int nf = 0; nf < 4; nf++) {
                int col = n0w + nf * 8 + tig * 2;
                float2 v0; v0.x = acc[mi][nf][0]; v0.y = acc[mi][nf][1];
                float2 v1; v1.x = acc[mi][nf][2]; v1.y = acc[mi][nf][3];
                *(float2*)(g_xg + row * G1 + col) = v0;
                *(float2*)(g_xg + (row + 8) * G1 + col) = v1;
            }
        }
        __syncthreads();   // all reads of X(tt) done before restaging
    }
}

// ======================= PHASE B (R12 config) =======================
__device__ __forceinline__ void stage1_step(
    int tn, int bg0, const float* __restrict__ W1HI,
    float* __restrict__ H1B, float4 (&xg)[4], float (&c1)[4],
    int j1, int b1) {
    const float* H1r = H1B + ((tn + 1) & 1) * H1SZ;
    float* H1w = H1B + (tn & 1) * H1SZ;

    const float* x0 = (const float*)&xg[0];
    const float* x1 = (const float*)&xg[1];
    const float* x2 = (const float*)&xg[2];
    const float* x3 = (const float*)&xg[3];
    u64 acc[4][2];
#pragma unroll
    for (int q = 0; q < 4; q++) {
        acc[q][0] = pack2(x0[q], x1[q]);
        acc[q][1] = pack2(x2[q], x3[q]);
    }
#pragma unroll 4
    for (int k = 0; k < H1; k++) {
        const float* wr = W1HI + k * G1 + 4 * j1;
        float4 w4 = *(const float4*)wr;
        u64 wd0 = pack2(w4.x, w4.x);
        u64 wd1 = pack2(w4.y, w4.y);
        u64 wd2 = pack2(w4.z, w4.z);
        u64 wd3 = pack2(w4.w, w4.w);
        ulonglong2 xv = *(const ulonglong2*)(H1r + k * HP + b1);
        acc[0][0] = fma2(xv.x, wd0, acc[0][0]);
        acc[0][1] = fma2(xv.y, wd0, acc[0][1]);
        acc[1][0] = fma2(xv.x, wd1, acc[1][0]);
        acc[1][1] = fma2(xv.y, wd1, acc[1][1]);
        acc[2][0] = fma2(xv.x, wd2, acc[2][0]);
        acc[2][1] = fma2(xv.y, wd2, acc[2][1]);
        acc[3][0] = fma2(xv.x, wd3, acc[3][0]);
        acc[3][1] = fma2(xv.y, wd3, acc[3][1]);
    }
    if (tn + 1 < TT) {
#pragma unroll
        for (int i = 0; i < 4; i++)
            xg[i] = *(const float4*)(g_xg +
                ((size_t)(bg0 + i) * TT + tn + 1) * G1 + 4 * j1);
    }
    float h4[4];
#pragma unroll
    for (int p = 0; p < 2; p++) {
        float2 ai = u2f2(acc[0][p]);
        float2 af = u2f2(acc[1][p]);
        float2 ag = u2f2(acc[2][p]);
        float2 ao = u2f2(acc[3][p]);
#pragma unroll
        for (int m = 0; m < 2; m++) {
            int e = 2 * p + m;
            float iv = sigf(m ? ai.y : ai.x);
            float fv = sigf(m ? af.y : af.x);
            float gv = tanhf_(m ? ag.y : ag.x);
            float ov = sigf(m ? ao.y : ao.x);
            float c = fv * c1[e] + iv * gv;
            c1[e] = c;
            h4[e] = ov * tanhf_(c);
        }
    }
    float4 hv; hv.x = h4[0]; hv.y = h4[1]; hv.z = h4[2]; hv.w = h4[3];
    *(float4*)(H1w + j1 * HP + b1) = hv;
}

extern __shared__ float smemB[];
__global__ __launch_bounds__(NTB, 2) void lstm_phaseB(
    const float* __restrict__ w_hh1,
    const float* __restrict__ w_ih2, const float* __restrict__ w_hh2,
    const float* __restrict__ b_ih2, const float* __restrict__ b_hh2,
    const float* __restrict__ w_ih3, const float* __restrict__ w_hh3,
    const float* __restrict__ b_ih3, const float* __restrict__ b_hh3,
    const float* __restrict__ fc_w, const float* __restrict__ fc_b,
    float* __restrict__ out) {
    const int tid = threadIdx.x;
    const int cta = blockIdx.x;

    float* W1HI = smemB + OFFB_W1HI;
    float* W2XI = smemB + OFFB_W2XI;
    float* W2HI = smemB + OFFB_W2HI;
    float* B2I  = smemB + OFFB_B2I;
    float* W3XI = smemB + OFFB_W3XI;
    float* W3HI = smemB + OFFB_W3HI;
    float* B3I  = smemB + OFFB_B3I;
    float* H1B  = smemB + OFFB_H1;
    float* H2B  = smemB + OFFB_H2;
    float* H3B  = smemB + OFFB_H3;

    for (int i = tid; i < G1 * H1; i += NTB) {
        int g = i >> 5, k = i & 31;
        W1HI[k * G1 + 4 * (g & 31) + (g >> 5)] = w_hh1[i];
    }
    for (int i = tid; i < G2 * H1; i += NTB) {
        int g = i >> 5, k = i & 31;
        W2XI[k * G2 + 4 * (g & 15) + (g >> 4)] = w_ih2[i];
    }
    for (int i = tid; i < G2 * H2; i += NTB) {
        int g = i >> 4, k = i & 15;
        W2HI[k * G2 + 4 * (g & 15) + (g >> 4)] = w_hh2[i];
    }
    for (int i = tid; i < G2; i += NTB)
        B2I[4 * (i & 15) + (i >> 4)] = b_ih2[i] + b_hh2[i];
    for (int i = tid; i < G3 * H2; i += NTB) {
        int g = i >> 4, k = i & 15;
        W3XI[k * G3 + 4 * (g & 7) + (g >> 3)] = w_ih3[i];
    }
    for (int i = tid; i < G3 * H3; i += NTB) {
        int g = i >> 3, k = i & 7;
        W3HI[k * G3 + 4 * (g & 7) + (g >> 3)] = w_hh3[i];
    }
    for (int i = tid; i < G3; i += NTB)
        B3I[4 * (i & 7) + (i >> 3)] = b_ih3[i] + b_hh3[i];
    for (int i = tid; i < 2 * H1SZ; i += NTB) H1B[i] = 0.f;
    for (int i = tid; i < 2 * H2SZ; i += NTB) H2B[i] = 0.f;
    for (int i = tid; i < 2 * H3SZ; i += NTB) H3B[i] = 0.f;

    // group A (warps 0-7): L1, 1 j x 4 batch.
    const int widA = tid >> 5;
    const int j1 = (widA & 1) * 16 + (tid & 15);
    const int b1 = (widA >> 1) * 8 + ((tid >> 4) & 1) * 4;
    const int bg0 = cta * BTB + b1;
    float c1[4] = {0.f, 0.f, 0.f, 0.f};
    float4 xg[4];

    // group B (warps 8-15)
    const int tid2 = tid - 256;
    const int j2 = tid2 >> 4;
    const int b2 = (tid2 & 15) * 2;
    const int j3 = tid2 >> 5;
    const int b3 = tid2 & 31;
    float c2[2] = {0.f, 0.f};
    float c3 = 0.f;

    if (tid < 256) {
#pragma unroll
        for (int i = 0; i < 4; i++)
            xg[i] = *(const float4*)(g_xg + (size_t)(bg0 + i) * TT * G1 + 4 * j1);
    }
    __syncthreads();

    if (tid < 256)
        stage1_step(0, bg0, W1HI, H1B, xg, c1, j1, b1);
    __syncthreads();

    for (int t = 0; t < TT; ++t) {
        if (tid < 256) {
            if (t + 1 < TT)
                stage1_step(t + 1, bg0, W1HI, H1B, xg, c1, j1, b1);
        } else {
            const float* H1t = H1B + (t & 1) * H1SZ;
            const float* H2r = H2B + ((t + 1) & 1) * H2SZ;
            float* H2w = H2B + (t & 1) * H2SZ;
            const float* H3r = H3B + ((t + 1) & 1) * H3SZ;
            float* H3w = H3B + (t & 1) * H3SZ;

            {
                u64 acc[4];
                float4 bv4 = *(const float4*)(B2I + 4 * j2);
                acc[0] = pack2(bv4.x, bv4.x);
                acc[1] = pack2(bv4.y, bv4.y);
                acc[2] = pack2(bv4.z, bv4.z);
                acc[3] = pack2(bv4.w, bv4.w);
#pragma unroll 4
                for (int k = 0; k < H1; k++) {
                    const float* wr = W2XI + k * G2 + 4 * j2;
                    float4 w4 = *(const float4*)wr;
                    u64 xv = *(const u64*)(H1t + k * HP + b2);
                    acc[0] = fma2(xv, pack2(w4.x, w4.x), acc[0]);
                    acc[1] = fma2(xv, pack2(w4.y, w4.y), acc[1]);
                    acc[2] = fma2(xv, pack2(w4.z, w4.z), acc[2]);
                    acc[3] = fma2(xv, pack2(w4.w, w4.w), acc[3]);
                }
#pragma unroll 4
                for (int k = 0; k < H2; k++) {
                    const float* wr = W2HI + k * G2 + 4 * j2;
                    float4 w4 = *(const float4*)wr;
                    u64 xv = *(const u64*)(H2r + k * HP + b2);
                    acc[0] = fma2(xv, pack2(w4.x, w4.x), acc[0]);
                    acc[1] = fma2(xv, pack2(w4.y, w4.y), acc[1]);
                    acc[2] = fma2(xv, pack2(w4.z, w4.z), acc[2]);
                    acc[3] = fma2(xv, pack2(w4.w, w4.w), acc[3]);
                }
                float2 ai = u2f2(acc[0]);
                float2 af = u2f2(acc[1]);
                float2 ag = u2f2(acc[2]);
                float2 ao = u2f2(acc[3]);
                float h2v[2];
#pragma unroll
                for (int m = 0; m < 2; m++) {
                    float iv = sigf(m ? ai.y : ai.x);
                    float fv = sigf(m ? af.y : af.x);
                    float gv = tanhf_(m ? ag.y : ag.x);
                    float ov = sigf(m ? ao.y : ao.x);
                    float c = fv * c2[m] + iv * gv;
                    c2[m] = c;
                    h2v[m] = ov * tanhf_(c);
                }
                float2 hv; hv.x = h2v[0]; hv.y = h2v[1];
                *(float2*)(H2w + j2 * HP + b2) = hv;
            }
            asm volatile("bar.sync 1, 256;" ::: "memory");

            {
                u64 aif = *(const u64*)(B3I + 4 * j3);
                u64 ago = *(const u64*)(B3I + 4 * j3 + 2);
#pragma unroll 4
                for (int k = 0; k < H2; k++) {
                    ulonglong2 w = *(const ulonglong2*)(W3XI + k * G3 + 4 * j3);
                    float s = H2w[k * HP + b3];
                    u64 ss = pack2(s, s);
                    aif = fma2(ss, w.x, aif);
                    ago = fma2(ss, w.y, ago);
                }
#pragma unroll
                for (int k = 0; k < H3; k++) {
                    ulonglong2 w = *(const ulonglong2*)(W3HI + k * G3 + 4 * j3);
                    float s = H3r[k * HP + b3];
                    u64 ss = pack2(s, s);
                    aif = fma2(ss, w.x, aif);
                    ago = fma2(ss, w.y, ago);
                }
                float2 vif = u2f2(aif), vgo = u2f2(ago);
                float iv = sigf(vif.x);
                float fv = sigf(vif.y);
                float gv = tanhf_(vgo.x);
                float ov = sigf(vgo.y);
                float c = fv * c3 + iv * gv;
                c3 = c;
                H3w[j3 * HP + b3] = ov * tanhf_(c);
            }
        }
        __syncthreads();
    }

    if (tid < BTB) {
        const float* H3f = H3B + H3SZ;
        float acc = fc_b[0];
#pragma unroll
        for (int j = 0; j < H3; j++) acc += fc_w[j] * H3f[j * HP + tid];
        out[cta * BTB + tid] = acc;
    }
}

extern "C" void kernel_launch(void* const* d_in, const int* in_sizes, int n_in,
                              void* d_out, int out_size) {
    (void)in_sizes; (void)n_in; (void)out_size;
    const float* x     = (const float*)d_in[0];
    const float* w_ih1 = (const float*)d_in[1];
    const float* w_hh1 = (const float*)d_in[2];
    const float* b_ih1 = (const float*)d_in[3];
    const float* b_hh1 = (const float*)d_in[4];
    const float* w_ih2 = (const float*)d_in[5];
    const float* w_hh2 = (const float*)d_in[6];
    const float* b_ih2 = (const float*)d_in[7];
    const float* b_hh2 = (const float*)d_in[8];
    const float* w_ih3 = (const float*)d_in[9];
    const float* w_hh3 = (const float*)d_in[10];
    const float* b_ih3 = (const float*)d_in[11];
    const float* b_hh3 = (const float*)d_in[12];
    const float* fc_w  = (const float*)d_in[13];
    const float* fc_b  = (const float*)d_in[14];
    float* out = (float*)d_out;

    cudaFuncSetAttribute(lstm_phaseA_mma,
                         cudaFuncAttributeMaxDynamicSharedMemorySize, A_SMEM_BYTES);
    cudaFuncSetAttribute(lstm_phaseB,
                         cudaFuncAttributeMaxDynamicSharedMemorySize, B_SMEM_BYTES);

    lstm_phaseA_mma<<<NBLK_A, NTM_A, A_SMEM_BYTES>>>(x, w_ih1, b_ih1, b_hh1);
    lstm_phaseB<<<NCTA_B, NTB, B_SMEM_BYTES>>>(
        w_hh1, w_ih2, w_hh2, b_ih2, b_hh2,
        w_ih3, w_hh3, b_ih3, b_hh3, fc_w, fc_b, out);
}

// round 17
// speedup vs baseline: 1.1021x; 1.1021x over previous
#include <cuda_runtime.h>
#include <cuda_fp16.h>
#include <cstdint>

typedef unsigned long long u64;

#define TT    64
#define BATCH 8192
#define DIN   128

#define G1 128
#define G2 64
#define G3 32
#define H1 32
#define H2 16
#define H3 8

// ---------------- phase A (mma.sync fp16 2-pass GEMM, M=64 tiles, dbuf X) ----------------
#define NTM_A 256
#define TPB_A 8
#define NBLK_A 1024                     // 8192 tiles / 8
#define PW 68                           // smem pitch in 32-bit words
#define XBUF_BYTES (64 * PW * 4)        // 17408 per X half-buffer
// layout: XH[0], XL[0], XH[1], XL[1], WH
#define XH_OFF(b) ((b) * 2 * XBUF_BYTES)
#define XL_OFF(b) ((b) * 2 * XBUF_BYTES + XBUF_BYTES)
#define WH_OFF    (4 * XBUF_BYTES)     // 69632
#define A_SMEM_BYTES (WH_OFF + 128 * PW * 4)   // 104448 -> 2 CTAs/SM

// ---------------- phase B (recurrent, BT=32, warp-specialized; R12 config) ----------------
#define BTB  32
#define NCTA_B (BATCH / BTB)
#define NTB 512
#define HP 36
#define H1SZ (H1 * HP)
#define H2SZ (H2 * HP)
#define H3SZ (H3 * HP)
#define OFFB_W1HI 0
#define OFFB_W2XI 4096
#define OFFB_W2HI 6144
#define OFFB_B2I  7168
#define OFFB_W3XI 7232
#define OFFB_W3HI 7744
#define OFFB_B3I  8000
#define OFFB_H1   8032
#define OFFB_H2   (OFFB_H1 + 2 * H1SZ)
#define OFFB_H3   (OFFB_H2 + 2 * H2SZ)
#define B_SMEM_FLOATS (OFFB_H3 + 2 * H3SZ)
#define B_SMEM_BYTES  (B_SMEM_FLOATS * 4)

// 256 MB scratch: XG[r = b*64 + t][n = 4j+q]  (row-major, bias folded in)
__device__ float g_xg[(size_t)BATCH * TT * G1];

// ======================= common helpers =======================
__device__ __forceinline__ u64 pack2(float a, float b) {
    u64 r;
    asm("mov.b64 %0, {%1, %2};" : "=l"(r) : "f"(a), "f"(b));
    return r;
}
__device__ __forceinline__ u64 fma2(u64 a, u64 b, u64 c) {
    u64 d;
    asm("fma.rn.f32x2 %0, %1, %2, %3;" : "=l"(d) : "l"(a), "l"(b), "l"(c));
    return d;
}
__device__ __forceinline__ float2 u2f2(u64 v) {
    float2 r;
    asm("mov.b64 {%0, %1}, %2;" : "=f"(r.x), "=f"(r.y) : "l"(v));
    return r;
}
__device__ __forceinline__ float sigf(float v) {
    return __fdividef(1.f, 1.f + __expf(-v));
}
__device__ __forceinline__ float tanhf_(float v) {
    return 1.f - __fdividef(2.f, __expf(2.f * v) + 1.f);
}

__device__ __forceinline__ void mma_f16(float (&d)[4],
                                        uint32_t a0, uint32_t a1,
                                        uint32_t a2, uint32_t a3,
                                        uint32_t b0, uint32_t b1) {
    asm volatile(
        "mma.sync.aligned.m16n8k16.row.col.f32.f16.f16.f32 "
        "{%0,%1,%2,%3}, {%4,%5,%6,%7}, {%8,%9}, {%0,%1,%2,%3};"
        : "+f"(d[0]), "+f"(d[1]), "+f"(d[2]), "+f"(d[3])
        : "r"(a0), "r"(a1), "r"(a2), "r"(a3), "r"(b0), "r"(b1));
}

// convert float4 into fp16 hi/lo half2 word pairs
__device__ __forceinline__ void cvt4hl(float4 v, uint32_t* H, uint32_t* L) {
    __half2 h0 = __float22half2_rn(make_float2(v.x, v.y));
    float2 f0 = __half22float2(h0);
    __half2 l0 = __float22half2_rn(make_float2(v.x - f0.x, v.y - f0.y));
    __half2 h1 = __float22half2_rn(make_float2(v.z, v.w));
    float2 f1 = __half22float2(h1);
    __half2 l1 = __float22half2_rn(make_float2(v.z - f1.x, v.w - f1.y));
    H[0] = *(uint32_t*)&h0;
    H[1] = *(uint32_t*)&h1;
    L[0] = *(uint32_t*)&l0;
    L[1] = *(uint32_t*)&l1;
}
// convert float4 into fp16 word pair (hi only)
__device__ __forceinline__ void cvt4h(float4 v, uint32_t* H) {
    __half2 h0 = __float22half2_rn(make_float2(v.x, v.y));
    __half2 h1 = __float22half2_rn(make_float2(v.z, v.w));
    H[0] = *(uint32_t*)&h0;
    H[1] = *(uint32_t*)&h1;
}

// ======================= PHASE A (HMMA fp16 2-pass, M=64, dbuf X) =======================
// XG[r][4j+q] = sum_k x[r][k] * w_ih1[q*32+j][k] + b1[q*32+j]
// x = xh + xl (fp16 split); W = fp16(W). D = xh@wh + xl@wh.
extern __shared__ char smA[];
__global__ __launch_bounds__(NTM_A, 2) void lstm_phaseA_mma(
    const float* __restrict__ x,
    const float* __restrict__ w_ih1,
    const float* __restrict__ b_ih1,
    const float* __restrict__ b_hh1) {
    uint32_t* WH = (uint32_t*)(smA + WH_OFF);

    const int tid = threadIdx.x;
    const int wid = tid >> 5, lid = tid & 31;
    const int g = lid >> 2, tig = lid & 3;
    const int m0w = (wid & 1) * 32;      // warp M offset (0 or 32)
    const int n0w = (wid >> 1) * 32;     // warp N offset (0..96)

    // bias for this thread's D columns (n, n+1) per n-frag
    float2 biasp[4];
#pragma unroll
    for (int nf = 0; nf < 4; nf++) {
        int n = n0w + nf * 8 + tig * 2;
        int ga = ((n & 3) << 5) + (n >> 2);
        int gb = (((n + 1) & 3) << 5) + ((n + 1) >> 2);
        biasp[nf].x = b_ih1[ga] + b_hh1[ga];
        biasp[nf].y = b_ih1[gb] + b_hh1[gb];
    }

    // stage W fp16 once: row n of W^T = w_ih1 row g(n)
    {
        int row = tid >> 1, c0 = (tid & 1) * 64;
        int gw = ((row & 3) << 5) + (row >> 2);
        const float* src = w_ih1 + (size_t)gw * DIN + c0;
        uint32_t* Hd = WH + row * PW + (c0 >> 1);
#pragma unroll
        for (int i = 0; i < 16; i++)
            cvt4h(((const float4*)src)[i], Hd + 2 * i);
    }

    // x staging: row = tid>>2 (0..63), c0 = (tid&3)*32
    const int xrow = tid >> 2;
    const int xc0 = (tid & 3) * 32;
    float4 xr[8];
#define LOADX_A(tt_)                                                        \
    {                                                                       \
        const float4* p = (const float4*)(x +                               \
            (((size_t)blockIdx.x * TPB_A + (tt_)) * 64 + xrow) * DIN + xc0); \
        _Pragma("unroll") for (int i = 0; i < 8; i++) xr[i] = p[i];         \
    }
#define STOREX_A(buf)                                                       \
    {                                                                       \
        uint32_t* Hd = (uint32_t*)(smA + XH_OFF(buf)) + xrow * PW + (xc0 >> 1); \
        uint32_t* Ld = (uint32_t*)(smA + XL_OFF(buf)) + xrow * PW + (xc0 >> 1); \
        _Pragma("unroll") for (int i = 0; i < 8; i++)                       \
            cvt4hl(xr[i], Hd + 2 * i, Ld + 2 * i);                          \
    }

    // prologue: stage tile 0 into buffer 0
    LOADX_A(0);
    STOREX_A(0);
    __syncthreads();   // W + X(0) staged

    for (int tt = 0; tt < TPB_A; tt++) {
        const size_t r0 = ((size_t)blockIdx.x * TPB_A + tt) * 64;
        const uint32_t* XH = (const uint32_t*)(smA + XH_OFF(tt & 1));
        const uint32_t* XL = (const uint32_t*)(smA + XL_OFF(tt & 1));

        // issue LDG for tile tt+1 first; latency covered by MMA below
        if (tt + 1 < TPB_A) LOADX_A(tt + 1);

        float acc[2][4][4];
#pragma unroll
        for (int mi = 0; mi < 2; mi++)
#pragma unroll
            for (int nf = 0; nf < 4; nf++) {
                acc[mi][nf][0] = biasp[nf].x;
                acc[mi][nf][1] = biasp[nf].y;
                acc[mi][nf][2] = biasp[nf].x;
                acc[mi][nf][3] = biasp[nf].y;
            }

#pragma unroll
        for (int ks = 0; ks < 8; ks++) {
            uint32_t ah[2][4], al[2][4];
#pragma unroll
            for (int mi = 0; mi < 2; mi++) {
                int base = (m0w + mi * 16 + g) * PW + tig + ks * 8;
                ah[mi][0] = XH[base];
                ah[mi][1] = XH[base + 8 * PW];
                ah[mi][2] = XH[base + 4];
                ah[mi][3] = XH[base + 8 * PW + 4];
                al[mi][0] = XL[base];
                al[mi][1] = XL[base + 8 * PW];
                al[mi][2] = XL[base + 4];
                al[mi][3] = XL[base + 8 * PW + 4];
            }
#pragma unroll
            for (int nf = 0; nf < 4; nf++) {
                int wb = (n0w + nf * 8 + g) * PW + tig + ks * 8;
                uint32_t bh0 = WH[wb], bh1 = WH[wb + 4];
#pragma unroll
                for (int mi = 0; mi < 2; mi++) {
                    mma_f16(acc[mi][nf], ah[mi][0], ah[mi][1], ah[mi][2], ah[mi][3], bh0, bh1);
                    mma_f16(acc[mi][nf], al[mi][0], al[mi][1], al[mi][2], al[mi][3], bh0, bh1);
                }
            }
        }

        // stage tile tt+1 into the other buffer (no barrier needed before:
        // buffer (tt+1)&1 was last read at iter tt-1, fenced by that barrier)
        if (tt + 1 < TPB_A) { STOREX_A((tt + 1) & 1); }

        // epilogue: D frags straight to row-major XG
#pragma unroll
        for (int mi = 0; mi < 2; mi++) {
            size_t row = r0 + m0w + mi * 16 + g;
#pragma unroll
            for (int nf = 0; nf < 4; nf++) {
                int col = n0w + nf * 8 + tig * 2;
                float2 v0; v0.x = acc[mi][nf][0]; v0.y = acc[mi][nf][1];
                float2 v1; v1.x = acc[mi][nf][2]; v1.y = acc[mi][nf][3];
                *(float2*)(g_xg + row * G1 + col) = v0;
                *(float2*)(g_xg + (row + 8) * G1 + col) = v1;
            }
        }
        __syncthreads();   // orders: reads of buf(tt&1) done; writes of buf((tt+1)&1) visible
    }
}

// ======================= PHASE B (R12 config) =======================
__device__ __forceinline__ void stage1_step(
    int tn, int bg0, const float* __restrict__ W1HI,
    float* __restrict__ H1B, float4 (&xg)[4], float (&c1)[4],
    int j1, int b1) {
    const float* H1r = H1B + ((tn + 1) & 1) * H1SZ;
    float* H1w = H1B + (tn & 1) * H1SZ;

    const float* x0 = (const float*)&xg[0];
    const float* x1 = (const float*)&xg[1];
    const float* x2 = (const float*)&xg[2];
    const float* x3 = (const float*)&xg[3];
    u64 acc[4][2];
#pragma unroll
    for (int q = 0; q < 4; q++) {
        acc[q][0] = pack2(x0[q], x1[q]);
        acc[q][1] = pack2(x2[q], x3[q]);
    }
#pragma unroll 4
    for (int k = 0; k < H1; k++) {
        const float* wr = W1HI + k * G1 + 4 * j1;
        float4 w4 = *(const float4*)wr;
        u64 wd0 = pack2(w4.x, w4.x);
        u64 wd1 = pack2(w4.y, w4.y);
        u64 wd2 = pack2(w4.z, w4.z);
        u64 wd3 = pack2(w4.w, w4.w);
        ulonglong2 xv = *(const ulonglong2*)(H1r + k * HP + b1);
        acc[0][0] = fma2(xv.x, wd0, acc[0][0]);
        acc[0][1] = fma2(xv.y, wd0, acc[0][1]);
        acc[1][0] = fma2(xv.x, wd1, acc[1][0]);
        acc[1][1] = fma2(xv.y, wd1, acc[1][1]);
        acc[2][0] = fma2(xv.x, wd2, acc[2][0]);
        acc[2][1] = fma2(xv.y, wd2, acc[2][1]);
        acc[3][0] = fma2(xv.x, wd3, acc[3][0]);
        acc[3][1] = fma2(xv.y, wd3, acc[3][1]);
    }
    if (tn + 1 < TT) {
#pragma unroll
        for (int i = 0; i < 4; i++)
            xg[i] = *(const float4*)(g_xg +
                ((size_t)(bg0 + i) * TT + tn + 1) * G1 + 4 * j1);
    }
    float h4[4];
#pragma unroll
    for (int p = 0; p < 2; p++) {
        float2 ai = u2f2(acc[0][p]);
        float2 af = u2f2(acc[1][p]);
        float2 ag = u2f2(acc[2][p]);
        float2 ao = u2f2(acc[3][p]);
#pragma unroll
        for (int m = 0; m < 2; m++) {
            int e = 2 * p + m;
            float iv = sigf(m ? ai.y : ai.x);
            float fv = sigf(m ? af.y : af.x);
            float gv = tanhf_(m ? ag.y : ag.x);
            float ov = sigf(m ? ao.y : ao.x);
            float c = fv * c1[e] + iv * gv;
            c1[e] = c;
            h4[e] = ov * tanhf_(c);
        }
    }
    float4 hv; hv.x = h4[0]; hv.y = h4[1]; hv.z = h4[2]; hv.w = h4[3];
    *(float4*)(H1w + j1 * HP + b1) = hv;
}

extern __shared__ float smemB[];
__global__ __launch_bounds__(NTB, 2) void lstm_phaseB(
    const float* __restrict__ w_hh1,
    const float* __restrict__ w_ih2, const float* __restrict__ w_hh2,
    const float* __restrict__ b_ih2, const float* __restrict__ b_hh2,
    const float* __restrict__ w_ih3, const float* __restrict__ w_hh3,
    const float* __restrict__ b_ih3, const float* __restrict__ b_hh3,
    const float* __restrict__ fc_w, const float* __restrict__ fc_b,
    float* __restrict__ out) {
    const int tid = threadIdx.x;
    const int cta = blockIdx.x;

    float* W1HI = smemB + OFFB_W1HI;
    float* W2XI = smemB + OFFB_W2XI;
    float* W2HI = smemB + OFFB_W2HI;
    float* B2I  = smemB + OFFB_B2I;
    float* W3XI = smemB + OFFB_W3XI;
    float* W3HI = smemB + OFFB_W3HI;
    float* B3I  = smemB + OFFB_B3I;
    float* H1B  = smemB + OFFB_H1;
    float* H2B  = smemB + OFFB_H2;
    float* H3B  = smemB + OFFB_H3;

    for (int i = tid; i < G1 * H1; i += NTB) {
        int g = i >> 5, k = i & 31;
        W1HI[k * G1 + 4 * (g & 31) + (g >> 5)] = w_hh1[i];
    }
    for (int i = tid; i < G2 * H1; i += NTB) {
        int g = i >> 5, k = i & 31;
        W2XI[k * G2 + 4 * (g & 15) + (g >> 4)] = w_ih2[i];
    }
    for (int i = tid; i < G2 * H2; i += NTB) {
        int g = i >> 4, k = i & 15;
        W2HI[k * G2 + 4 * (g & 15) + (g >> 4)] = w_hh2[i];
    }
    for (int i = tid; i < G2; i += NTB)
        B2I[4 * (i & 15) + (i >> 4)] = b_ih2[i] + b_hh2[i];
    for (int i = tid; i < G3 * H2; i += NTB) {
        int g = i >> 4, k = i & 15;
        W3XI[k * G3 + 4 * (g & 7) + (g >> 3)] = w_ih3[i];
    }
    for (int i = tid; i < G3 * H3; i += NTB) {
        int g = i >> 3, k = i & 7;
        W3HI[k * G3 + 4 * (g & 7) + (g >> 3)] = w_hh3[i];
    }
    for (int i = tid; i < G3; i += NTB)
        B3I[4 * (i & 7) + (i >> 3)] = b_ih3[i] + b_hh3[i];
    for (int i = tid; i < 2 * H1SZ; i += NTB) H1B[i] = 0.f;
    for (int i = tid; i < 2 * H2SZ; i += NTB) H2B[i] = 0.f;
    for (int i = tid; i < 2 * H3SZ; i += NTB) H3B[i] = 0.f;

    // group A (warps 0-7): L1, 1 j x 4 batch.
    const int widA = tid >> 5;
    const int j1 = (widA & 1) * 16 + (tid & 15);
    const int b1 = (widA >> 1) * 8 + ((tid >> 4) & 1) * 4;
    const int bg0 = cta * BTB + b1;
    float c1[4] = {0.f, 0.f, 0.f, 0.f};
    float4 xg[4];

    // group B (warps 8-15)
    const int tid2 = tid - 256;
    const int j2 = tid2 >> 4;
    const int b2 = (tid2 & 15) * 2;
    const int j3 = tid2 >> 5;
    const int b3 = tid2 & 31;
    float c2[2] = {0.f, 0.f};
    float c3 = 0.f;

    if (tid < 256) {
#pragma unroll
        for (int i = 0; i < 4; i++)
            xg[i] = *(const float4*)(g_xg + (size_t)(bg0 + i) * TT * G1 + 4 * j1);
    }
    __syncthreads();

    if (tid < 256)
        stage1_step(0, bg0, W1HI, H1B, xg, c1, j1, b1);
    __syncthreads();

    for (int t = 0; t < TT; ++t) {
        if (tid < 256) {
            if (t + 1 < TT)
                stage1_step(t + 1, bg0, W1HI, H1B, xg, c1, j1, b1);
        } else {
            const float* H1t = H1B + (t & 1) * H1SZ;
            const float* H2r = H2B + ((t + 1) & 1) * H2SZ;
            float* H2w = H2B + (t & 1) * H2SZ;
            const float* H3r = H3B + ((t + 1) & 1) * H3SZ;
            float* H3w = H3B + (t & 1) * H3SZ;

            {
                u64 acc[4];
                float4 bv4 = *(const float4*)(B2I + 4 * j2);
                acc[0] = pack2(bv4.x, bv4.x);
                acc[1] = pack2(bv4.y, bv4.y);
                acc[2] = pack2(bv4.z, bv4.z);
                acc[3] = pack2(bv4.w, bv4.w);
#pragma unroll 4
                for (int k = 0; k < H1; k++) {
                    const float* wr = W2XI + k * G2 + 4 * j2;
                    float4 w4 = *(const float4*)wr;
                    u64 xv = *(const u64*)(H1t + k * HP + b2);
                    acc[0] = fma2(xv, pack2(w4.x, w4.x), acc[0]);
                    acc[1] = fma2(xv, pack2(w4.y, w4.y), acc[1]);
                    acc[2] = fma2(xv, pack2(w4.z, w4.z), acc[2]);
                    acc[3] = fma2(xv, pack2(w4.w, w4.w), acc[3]);
                }
#pragma unroll 4
                for (int k = 0; k < H2; k++) {
                    const float* wr = W2HI + k * G2 + 4 * j2;
                    float4 w4 = *(const float4*)wr;
                    u64 xv = *(const u64*)(H2r + k * HP + b2);
                    acc[0] = fma2(xv, pack2(w4.x, w4.x), acc[0]);
                    acc[1] = fma2(xv, pack2(w4.y, w4.y), acc[1]);
                    acc[2] = fma2(xv, pack2(w4.z, w4.z), acc[2]);
                    acc[3] = fma2(xv, pack2(w4.w, w4.w), acc[3]);
                }
                float2 ai = u2f2(acc[0]);
                float2 af = u2f2(acc[1]);
                float2 ag = u2f2(acc[2]);
                float2 ao = u2f2(acc[3]);
                float h2v[2];
#pragma unroll
                for (int m = 0; m < 2; m++) {
                    float iv = sigf(m ? ai.y : ai.x);
                    float fv = sigf(m ? af.y : af.x);
                    float gv = tanhf_(m ? ag.y : ag.x);
                    float ov = sigf(m ? ao.y : ao.x);
                    float c = fv * c2[m] + iv * gv;
                    c2[m] = c;
                    h2v[m] = ov * tanhf_(c);
                }
                float2 hv; hv.x = h2v[0]; hv.y = h2v[1];
                *(float2*)(H2w + j2 * HP + b2) = hv;
            }
            asm volatile("bar.sync 1, 256;" ::: "memory");

            {
                u64 aif = *(const u64*)(B3I + 4 * j3);
                u64 ago = *(const u64*)(B3I + 4 * j3 + 2);
#pragma unroll 4
                for (int k = 0; k < H2; k++) {
                    ulonglong2 w = *(const ulonglong2*)(W3XI + k * G3 + 4 * j3);
                    float s = H2w[k * HP + b3];
                    u64 ss = pack2(s, s);
                    aif = fma2(ss, w.x, aif);
                    ago = fma2(ss, w.y, ago);
                }
#pragma unroll
                for (int k = 0; k < H3; k++) {
                    ulonglong2 w = *(const ulonglong2*)(W3HI + k * G3 + 4 * j3);
                    float s = H3r[k * HP + b3];
                    u64 ss = pack2(s, s);
                    aif = fma2(ss, w.x, aif);
                    ago = fma2(ss, w.y, ago);
                }
                float2 vif = u2f2(aif), vgo = u2f2(ago);
                float iv = sigf(vif.x);
                float fv = sigf(vif.y);
                float gv = tanhf_(vgo.x);
                float ov = sigf(vgo.y);
                float c = fv * c3 + iv * gv;
                c3 = c;
                H3w[j3 * HP + b3] = ov * tanhf_(c);
            }
        }
        __syncthreads();
    }

    if (tid < BTB) {
        const float* H3f = H3B + H3SZ;
        float acc = fc_b[0];
#pragma unroll
        for (int j = 0; j < H3; j++) acc += fc_w[j] * H3f[j * HP + tid];
        out[cta * BTB + tid] = acc;
    }
}

extern "C" void kernel_launch(void* const* d_in, const int* in_sizes, int n_in,
                              void* d_out, int out_size) {
    (void)in_sizes; (void)n_in; (void)out_size;
    const float* x     = (const float*)d_in[0];
    const float* w_ih1 = (const float*)d_in[1];
    const float* w_hh1 = (const float*)d_in[2];
    const float* b_ih1 = (const float*)d_in[3];
    const float* b_hh1 = (const float*)d_in[4];
    const float* w_ih2 = (const float*)d_in[5];
    const float* w_hh2 = (const float*)d_in[6];
    const float* b_ih2 = (const float*)d_in[7];
    const float* b_hh2 = (const float*)d_in[8];
    const float* w_ih3 = (const float*)d_in[9];
    const float* w_hh3 = (const float*)d_in[10];
    const float* b_ih3 = (const float*)d_in[11];
    const float* b_hh3 = (const float*)d_in[12];
    const float* fc_w  = (const float*)d_in[13];
    const float* fc_b  = (const float*)d_in[14];
    float* out = (float*)d_out;

    cudaFuncSetAttribute(lstm_phaseA_mma,
                         cudaFuncAttributeMaxDynamicSharedMemorySize, A_SMEM_BYTES);
    cudaFuncSetAttribute(lstm_phaseB,
                         cudaFuncAttributeMaxDynamicSharedMemorySize, B_SMEM_BYTES);

    lstm_phaseA_mma<<<NBLK_A, NTM_A, A_SMEM_BYTES>>>(x, w_ih1, b_ih1, b_hh1);
    lstm_phaseB<<<NCTA_B, NTB, B_SMEM_BYTES>>>(
        w_hh1, w_ih2, w_hh2, b_ih2, b_hh2,
        w_ih3, w_hh3, b_ih3, b_hh3, fc_w, fc_b, out);
}